// round 1
// baseline (speedup 1.0000x reference)
#include <cuda_runtime.h>
#include <cuda_bf16.h>
#include <math.h>

// Problem constants
#define BATCH 32
#define NTOK  16384
#define DIM   64
#define NC    36          // FG_NUM + BG_NUM
#define ALPHA 10.0f
#define EPS   1e-12f

#define SPLIT 8           // blocks per batch
#define TILE  128         // tokens per tile
#define TILES_PER_BLOCK (NTOK / SPLIT / TILE)   // 16
#define NTHREADS 288      // 9 warps: 9 c-groups of 4 clusters

// Padded strides
#define CN_STRIDE 40      // cn rows padded to 40 (float4-aligned groups of 4)
#define XT_STRIDE 129     // xsT rows, odd stride -> conflict-free lane access
#define AP_STRIDE 40      // assign rows (float4 aligned)
#define P_STRIDE  37      // p rows (odd -> conflict-free scalar)

// Shared memory carve (floats)
#define SM_XST   0
#define SM_CN    (SM_XST + 64 * XT_STRIDE)        // 8256
#define SM_AP    (SM_CN  + 64 * CN_STRIDE)        // 10816
#define SM_P     (SM_AP  + TILE * AP_STRIDE)      // 15936
#define SM_RINV  (SM_P   + TILE * P_STRIDE)       // 20672
#define SM_TOTAL (SM_RINV + TILE)                 // 20800 floats = 83200 B

// Device-global scratch (no allocation allowed; statics are fine)
__device__ float g_cn[64 * CN_STRIDE];                       // normalized centroids, padded
__device__ float g_part_ws[BATCH * SPLIT * DIM * NC];        // per-block partial weighted sums
__device__ float g_part_sp[BATCH * SPLIT * NC];              // per-block partial self products

// ---------------------------------------------------------------------------
// Kernel 1: normalize centroids columns (d-axis) into padded g_cn
// ---------------------------------------------------------------------------
__global__ void vlad_prep(const float* __restrict__ centroids) {
    int c = threadIdx.x;
    if (c < NC) {
        float s = 0.f;
        #pragma unroll
        for (int d = 0; d < DIM; ++d) {
            float v = centroids[d * NC + c];
            s += v * v;
        }
        float r = 1.0f / fmaxf(sqrtf(s), EPS);
        #pragma unroll
        for (int d = 0; d < DIM; ++d) {
            g_cn[d * CN_STRIDE + c] = centroids[d * NC + c] * r;
        }
    } else if (c < CN_STRIDE) {
        // zero pad columns 36..39 so float4 loads are clean
        for (int d = 0; d < DIM; ++d) g_cn[d * CN_STRIDE + c] = 0.f;
    }
}

// ---------------------------------------------------------------------------
// Kernel 2: main — per-tile cos GEMM + softmax + weighted-sum GEMM
// grid: (SPLIT, BATCH), block: 288 threads, dyn smem 83200 B
// ---------------------------------------------------------------------------
__global__ void __launch_bounds__(NTHREADS, 2)
vlad_main(const float* __restrict__ x) {
    extern __shared__ float sm[];
    float* xsT   = sm + SM_XST;    // [64][129]  raw x transposed (k-major)
    float* cn_s  = sm + SM_CN;     // [64][40]   normalized centroids
    float* ap_s  = sm + SM_AP;     // [128][40]  cos -> rinv*assign
    float* p_s   = sm + SM_P;      // [128][37]  cos*assign
    float* rinv_s= sm + SM_RINV;   // [128]

    const int tid  = threadIdx.x;
    const int lane = tid & 31;
    const int w    = tid >> 5;       // warp id 0..8 -> cluster group c0 = 4*w
    const int b    = blockIdx.y;
    const int bx   = blockIdx.x;

    // load normalized centroids to smem
    for (int i = tid; i < 64 * CN_STRIDE; i += NTHREADS) cn_s[i] = g_cn[i];

    // phase-2 accumulators (persist across all tiles): d in {lane, lane+32}, c in {4w..4w+3}
    float acc2[8] = {0.f,0.f,0.f,0.f,0.f,0.f,0.f,0.f};
    float sp_acc = 0.f;   // threads < 36 accumulate self-product per cluster

    const float* xb = x + ((size_t)b * NTOK + (size_t)bx * (NTOK / SPLIT)) * DIM;

    for (int tile = 0; tile < TILES_PER_BLOCK; ++tile) {
        const float4* xt = (const float4*)(xb + (size_t)tile * TILE * DIM);

        __syncthreads();   // protect previous tile's consumers

        // ---- load + transpose: 128 tokens x 64 dims = 2048 float4 ----
        for (int i = tid; i < TILE * DIM / 4; i += NTHREADS) {
            float4 v = xt[i];
            int t = i >> 4;          // token in tile
            int k = (i & 15) << 2;   // dim base
            xsT[(k + 0) * XT_STRIDE + t] = v.x;
            xsT[(k + 1) * XT_STRIDE + t] = v.y;
            xsT[(k + 2) * XT_STRIDE + t] = v.z;
            xsT[(k + 3) * XT_STRIDE + t] = v.w;
        }
        __syncthreads();

        // ---- per-token inverse L2 norm (threads 0..127) ----
        if (tid < TILE) {
            float s = 0.f;
            #pragma unroll 16
            for (int k = 0; k < DIM; ++k) {
                float v = xsT[k * XT_STRIDE + tid];
                s += v * v;
            }
            rinv_s[tid] = 1.0f / fmaxf(sqrtf(s), EPS);
        }

        // ---- phase 1: cos GEMM  cos[t][c] = sum_k x[t][k]*cn[k][c] ----
        // lane -> tokens {lane, +32, +64, +96}; warp -> clusters {4w..4w+3}
        {
            float a[4][4];
            #pragma unroll
            for (int i = 0; i < 4; ++i)
                #pragma unroll
                for (int j = 0; j < 4; ++j) a[i][j] = 0.f;

            #pragma unroll 4
            for (int k = 0; k < DIM; ++k) {
                const float* xr = xsT + k * XT_STRIDE + lane;
                float x0 = xr[0], x1 = xr[32], x2 = xr[64], x3 = xr[96];
                float4 cv = *(const float4*)(cn_s + k * CN_STRIDE + (w << 2));
                a[0][0] += x0*cv.x; a[0][1] += x0*cv.y; a[0][2] += x0*cv.z; a[0][3] += x0*cv.w;
                a[1][0] += x1*cv.x; a[1][1] += x1*cv.y; a[1][2] += x1*cv.z; a[1][3] += x1*cv.w;
                a[2][0] += x2*cv.x; a[2][1] += x2*cv.y; a[2][2] += x2*cv.z; a[2][3] += x2*cv.w;
                a[3][0] += x3*cv.x; a[3][1] += x3*cv.y; a[3][2] += x3*cv.z; a[3][3] += x3*cv.w;
            }
            #pragma unroll
            for (int i = 0; i < 4; ++i) {
                int t = lane + 32 * i;
                #pragma unroll
                for (int j = 0; j < 4; ++j)
                    ap_s[t * AP_STRIDE + (w << 2) + j] = a[i][j];
            }
        }
        __syncthreads();

        // ---- softmax (threads 0..127): produce rinv*assign and cos*assign ----
        if (tid < TILE) {
            const int t = tid;
            float cv[NC];
            #pragma unroll
            for (int j = 0; j < NC / 4; ++j) {
                float4 v = *(const float4*)(ap_s + t * AP_STRIDE + 4 * j);
                cv[4*j+0] = v.x; cv[4*j+1] = v.y; cv[4*j+2] = v.z; cv[4*j+3] = v.w;
            }
            float ri = rinv_s[t];
            float m = -1e30f;
            #pragma unroll
            for (int j = 0; j < NC; ++j) { cv[j] *= ri; m = fmaxf(m, cv[j]); }
            float s = 0.f;
            #pragma unroll
            for (int j = 0; j < NC; ++j) {
                float e = __expf(ALPHA * (cv[j] - m));
                s += e;
                p_s[t * P_STRIDE + j] = cv[j] * e;   // cos*e (scale by 1/s below)
                cv[j] = e;
            }
            float is  = 1.0f / s;
            float ris = ri * is;
            #pragma unroll
            for (int j = 0; j < NC; ++j) {
                ap_s[t * AP_STRIDE + j] = cv[j] * ris;   // rinv * assign
                p_s[t * P_STRIDE + j]  *= is;            // cos  * assign
            }
        }
        __syncthreads();

        // ---- phase 2: ws[d][c] += sum_t x[t][d] * (rinv*assign)[t][c] ----
        // lane -> d in {lane, lane+32}; warp -> clusters {4w..4w+3}
        {
            #pragma unroll 4
            for (int t = 0; t < TILE; ++t) {
                float x0 = xsT[lane * XT_STRIDE + t];
                float x1 = xsT[(lane + 32) * XT_STRIDE + t];
                float4 av = *(const float4*)(ap_s + t * AP_STRIDE + (w << 2));
                acc2[0] += x0*av.x; acc2[1] += x0*av.y; acc2[2] += x0*av.z; acc2[3] += x0*av.w;
                acc2[4] += x1*av.x; acc2[5] += x1*av.y; acc2[6] += x1*av.z; acc2[7] += x1*av.w;
            }
        }

        // ---- self-product reduction (threads 0..35) ----
        if (tid < NC) {
            float s = 0.f;
            #pragma unroll 8
            for (int t = 0; t < TILE; ++t) s += p_s[t * P_STRIDE + tid];
            sp_acc += s;
        }
    }

    // ---- write per-block partials (deterministic, no atomics) ----
    const int slot = b * SPLIT + bx;
    float* wsp = g_part_ws + (size_t)slot * (DIM * NC);
    #pragma unroll
    for (int j = 0; j < 4; ++j) {
        wsp[lane        * NC + (w << 2) + j] = acc2[j];
        wsp[(lane + 32) * NC + (w << 2) + j] = acc2[4 + j];
    }
    if (tid < NC) g_part_sp[slot * NC + tid] = sp_acc;
}

// ---------------------------------------------------------------------------
// Kernel 3: finalize — reduce partials, projection, per-cluster + global L2
// grid: BATCH blocks, 256 threads
// ---------------------------------------------------------------------------
__global__ void vlad_finalize(float* __restrict__ out) {
    __shared__ float vl[NC * DIM];
    __shared__ float tot;
    const int tid  = threadIdx.x;
    const int lane = tid & 31;
    const int w    = tid >> 5;    // 8 warps
    const int b    = blockIdx.x;

    if (tid == 0) tot = 0.f;
    __syncthreads();

    float local = 0.f;
    for (int c = w; c < NC; c += 8) {
        float spc = 0.f;
        #pragma unroll
        for (int s = 0; s < SPLIT; ++s)
            spc += g_part_sp[(b * SPLIT + s) * NC + c];

        int d0 = lane, d1 = lane + 32;
        float v0 = 0.f, v1 = 0.f;
        #pragma unroll
        for (int s = 0; s < SPLIT; ++s) {
            const float* wsp = g_part_ws + (size_t)(b * SPLIT + s) * (DIM * NC);
            v0 += wsp[d0 * NC + c];
            v1 += wsp[d1 * NC + c];
        }
        v0 -= g_cn[d0 * CN_STRIDE + c] * spc;
        v1 -= g_cn[d1 * CN_STRIDE + c] * spc;

        float ss = v0 * v0 + v1 * v1;
        #pragma unroll
        for (int off = 16; off > 0; off >>= 1)
            ss += __shfl_xor_sync(0xffffffffu, ss, off);

        float r = 1.0f / fmaxf(sqrtf(ss), EPS);
        vl[c * DIM + d0] = v0 * r;
        vl[c * DIM + d1] = v1 * r;
        if (lane == 0) local += ss * r * r;   // sum of squares after row-normalize
    }
    if (lane == 0) atomicAdd(&tot, local);
    __syncthreads();

    float rt = 1.0f / fmaxf(sqrtf(tot), EPS);
    // output = first FG_NUM(=32) clusters of the globally-normalized vlad
    for (int i = tid; i < 32 * DIM; i += 256)
        out[b * (32 * DIM) + i] = vl[i] * rt;
}

// ---------------------------------------------------------------------------
extern "C" void kernel_launch(void* const* d_in, const int* in_sizes, int n_in,
                              void* d_out, int out_size) {
    const float* x         = (const float*)d_in[0];   // (32, 16384, 64) fp32
    const float* centroids = (const float*)d_in[1];   // (64, 36) fp32
    float* out             = (float*)d_out;           // (32, 2048) fp32

    (void)in_sizes; (void)n_in; (void)out_size;

    cudaFuncSetAttribute(vlad_main, cudaFuncAttributeMaxDynamicSharedMemorySize,
                         SM_TOTAL * (int)sizeof(float));

    vlad_prep<<<1, 64>>>(centroids);
    vlad_main<<<dim3(SPLIT, BATCH), NTHREADS, SM_TOTAL * sizeof(float)>>>(x);
    vlad_finalize<<<BATCH, 256>>>(out);
}

// round 7
// speedup vs baseline: 1.0347x; 1.0347x over previous
#include <cuda_runtime.h>
#include <cuda_bf16.h>
#include <math.h>

// ---------------------------------------------------------------------------
// Problem constants
// ---------------------------------------------------------------------------
#define BATCH 32
#define NTOK  16384
#define DIM   64
#define NC    36          // FG_NUM + BG_NUM
#define NCP   40          // padded cluster count (4 zero dummies)
#define FG    32
#define ALPHA 10.0f
#define EPS   1e-12f
#define LOG2E 1.4426950408889634f

#define SPLIT 32          // CTAs per batch -> 1024 CTAs total (~1% wave tail)
#define TILE  128         // tokens per tile
#define TILES_PER_CTA (NTOK / SPLIT / TILE)   // 4
#define NT    128         // 4 warps

// Strides (floats)
#define XS_STRIDE  68     // 17 x 16B (odd) -> conflict-free row float4 AND column scalar
#define CNT_STRIDE 64     // broadcast reads only
#define AP_STRIDE  44     // 11 x 16B (odd) -> conflict-free STS.128 rows, 40 payload

// Shared memory carve (floats)
#define SM_XS  0
#define SM_CNT (SM_XS  + TILE * XS_STRIDE)     // 8704
#define SM_AP  (SM_CNT + NC * CNT_STRIDE)      // 11008
#define SM_TOT (SM_AP  + TILE * AP_STRIDE)     // 16640 floats = 66560 B -> occ 3

// Device-global scratch (static; no allocation)
__device__ float g_ws[BATCH * SPLIT * DIM * NC];   // per-CTA partial weighted sums (9.4 MB)

// ---------------------------------------------------------------------------
// f32x2 packed helpers (PTX ISA 8.6, sm_100+)
// ---------------------------------------------------------------------------
typedef unsigned long long u64;

__device__ __forceinline__ u64 pk(float a, float b) {
    u64 r; asm("mov.b64 %0, {%1, %2};" : "=l"(r) : "f"(a), "f"(b)); return r;
}
__device__ __forceinline__ void upk(u64 v, float& a, float& b) {
    asm("mov.b64 {%0, %1}, %2;" : "=f"(a), "=f"(b) : "l"(v));
}
__device__ __forceinline__ u64 fma2(u64 a, u64 b, u64 c) {
    u64 d; asm("fma.rn.f32x2 %0, %1, %2, %3;" : "=l"(d) : "l"(a), "l"(b), "l"(c)); return d;
}
__device__ __forceinline__ float ex2f(float x) {
    float r; asm("ex2.approx.f32 %0, %1;" : "=f"(r) : "f"(x)); return r;
}

// ---------------------------------------------------------------------------
// Main kernel: grid (SPLIT, BATCH), 128 threads, 66560 B dyn smem, occ 3
// Phase 1: thread owns token t=tid; full cos row + fused softmax in registers.
// Phase 2: thread owns (d = tid&63, cluster-half of 20 = tid>>6), f32x2 over c.
// ---------------------------------------------------------------------------
__global__ void __launch_bounds__(NT, 3)
vlad_main(const float* __restrict__ x, const float* __restrict__ cent) {
    extern __shared__ float sm[];
    float* xs  = sm + SM_XS;    // [128][68] token-major raw x
    float* cnT = sm + SM_CNT;   // [36][64]  normalized centroids, c-major rows
    float* ap  = sm + SM_AP;    // [128][44] rinv * assign (40 payload, 4 zeros)

    const int tid = threadIdx.x;
    const int b   = blockIdx.y;
    const int bx  = blockIdx.x;

    // ---- normalize centroids into cnT (threads 0..35) ----
    if (tid < NC) {
        float ss = 0.f;
        for (int d = 0; d < DIM; ++d) { float v = cent[d * NC + tid]; ss += v * v; }
        float r = 1.0f / fmaxf(sqrtf(ss), EPS);
        for (int d = 0; d < DIM; ++d) cnT[tid * CNT_STRIDE + d] = cent[d * NC + tid] * r;
    }

    const int dd = tid & 63;     // dim owned in phase 2
    const int ch = tid >> 6;     // cluster half: 0 -> c 0..19, 1 -> c 20..39

    u64 acc[10];                 // persistent ws accumulators: 10 c-pairs (last of ch1 dummy)
    #pragma unroll
    for (int j = 0; j < 10; ++j) acc[j] = pk(0.f, 0.f);

    const float* xb = x + ((size_t)b * NTOK + (size_t)bx * (NTOK / SPLIT)) * DIM;

    for (int tile = 0; tile < TILES_PER_CTA; ++tile) {
        const float4* xt = (const float4*)(xb + (size_t)tile * TILE * DIM);

        __syncthreads();   // protect xs/ap consumers of previous tile (and cnT init)

        // ---- load tile: 2048 float4, coalesced LDG.128 -> conflict-free STS.128 ----
        #pragma unroll
        for (int j = 0; j < 16; ++j) {
            int i = tid + NT * j;
            float4 v = xt[i];
            int t = i >> 4, k = (i & 15) << 2;
            *(float4*)(xs + t * XS_STRIDE + k) = v;
        }
        __syncthreads();

        // ---- phase 1 + fused softmax: thread owns token t = tid ----
        {
            const int t = tid;
            u64 xp[32];
            #pragma unroll
            for (int j = 0; j < 16; ++j) {
                float4 v = *(const float4*)(xs + t * XS_STRIDE + 4 * j);
                xp[2*j]   = pk(v.x, v.y);
                xp[2*j+1] = pk(v.z, v.w);
            }
            // inverse L2 norm from registers
            u64 n0 = pk(0.f,0.f), n1 = pk(0.f,0.f);
            #pragma unroll
            for (int j = 0; j < 32; j += 2) {
                n0 = fma2(xp[j],   xp[j],   n0);
                n1 = fma2(xp[j+1], xp[j+1], n1);
            }
            float a0,a1,a2,a3; upk(n0,a0,a1); upk(n1,a2,a3);
            const float rinv = 1.0f / fmaxf(sqrtf((a0+a1)+(a2+a3)), EPS);

            // cos row: cn rows are warp-broadcast LDS.128
            float cv[NCP];
            #pragma unroll
            for (int c = 0; c < NC; ++c) {
                const float4* cr = (const float4*)(cnT + c * CNT_STRIDE);
                u64 s0 = pk(0.f,0.f), s1 = pk(0.f,0.f);
                #pragma unroll
                for (int j = 0; j < 16; ++j) {
                    float4 w = cr[j];
                    s0 = fma2(xp[2*j],   pk(w.x, w.y), s0);
                    s1 = fma2(xp[2*j+1], pk(w.z, w.w), s1);
                }
                upk(s0,a0,a1); upk(s1,a2,a3);
                cv[c] = ((a0+a1)+(a2+a3)) * rinv;
            }
            // softmax over the 36 real clusters
            float m = cv[0];
            #pragma unroll
            for (int c = 1; c < NC; ++c) m = fmaxf(m, cv[c]);
            float s = 0.f;
            #pragma unroll
            for (int c = 0; c < NC; ++c) {
                float e = ex2f((ALPHA * LOG2E) * (cv[c] - m));
                s += e; cv[c] = e;
            }
            cv[36] = 0.f; cv[37] = 0.f; cv[38] = 0.f; cv[39] = 0.f;
            const float ris = rinv / s;
            float* aprow = ap + t * AP_STRIDE;
            #pragma unroll
            for (int c = 0; c < NCP; c += 4)   // 10 conflict-free STS.128
                *(float4*)(aprow + c) = make_float4(cv[c]*ris, cv[c+1]*ris,
                                                    cv[c+2]*ris, cv[c+3]*ris);
        }
        __syncthreads();

        // ---- phase 2: ws[dd][c-pair] += x[t][dd] * a[t][c-pair] ----
        // 5 broadcast LDS.128 + 1 scalar LDS + 10 FFMA2 per token
        {
            const float* xcol  = xs + dd;           // conflict-free column scalars
            const float* abase = ap + ch * 20;      // 16B-aligned broadcast rows
            #pragma unroll 4
            for (int t = 0; t < TILE; ++t) {
                float xv = xcol[t * XS_STRIDE];
                u64 x2 = pk(xv, xv);
                const float* ar = abase + t * AP_STRIDE;
                #pragma unroll
                for (int j = 0; j < 5; ++j) {
                    float4 av = *(const float4*)(ar + 4 * j);
                    acc[2*j]   = fma2(x2, pk(av.x, av.y), acc[2*j]);
                    acc[2*j+1] = fma2(x2, pk(av.z, av.w), acc[2*j+1]);
                }
            }
        }
    }

    // ---- write per-CTA partials (deterministic); ch1 drops the 2 dummy pairs ----
    float* wsp = g_ws + (size_t)(b * SPLIT + bx) * (DIM * NC) + dd * NC + ch * 20;
    const int npair = (ch == 0) ? 10 : 8;   // ch1 covers c20..35
    for (int j = 0; j < npair; ++j) {
        float lo, hi; upk(acc[j], lo, hi);
        ((float2*)wsp)[j] = make_float2(lo, hi);
    }
}

// ---------------------------------------------------------------------------
// Finalize: reduce partials, self-product identity, projection, L2 norms.
// sp[c] = sum_d cn[d][c] * ws[d][c]  (exact rearrangement of sum_n cos*assign)
// grid: BATCH, 256 threads
// ---------------------------------------------------------------------------
__global__ void vlad_finalize(const float* __restrict__ cent, float* __restrict__ out) {
    __shared__ float cnF[NC * DIM];
    __shared__ float vl[NC * DIM];
    __shared__ float wsum[8];
    const int tid  = threadIdx.x;
    const int lane = tid & 31;
    const int w    = tid >> 5;    // 8 warps
    const int b    = blockIdx.x;

    if (tid < NC) {
        float ss = 0.f;
        for (int d = 0; d < DIM; ++d) { float v = cent[d * NC + tid]; ss += v * v; }
        float r = 1.0f / fmaxf(sqrtf(ss), EPS);
        for (int d = 0; d < DIM; ++d) cnF[tid * DIM + d] = cent[d * NC + tid] * r;
    }
    __syncthreads();

    float local = 0.f;
    for (int c = w; c < NC; c += 8) {
        const int d0 = lane, d1 = lane + 32;
        float v0 = 0.f, v1 = 0.f;
        #pragma unroll 4
        for (int s = 0; s < SPLIT; ++s) {
            const float* wsp = g_ws + (size_t)(b * SPLIT + s) * (DIM * NC);
            v0 += wsp[d0 * NC + c];
            v1 += wsp[d1 * NC + c];
        }
        const float c0 = cnF[c * DIM + d0], c1 = cnF[c * DIM + d1];

        // self-product via identity, warp-reduced over d
        float sp = c0 * v0 + c1 * v1;
        #pragma unroll
        for (int o = 16; o > 0; o >>= 1) sp += __shfl_xor_sync(0xffffffffu, sp, o);

        v0 -= c0 * sp;
        v1 -= c1 * sp;

        float ss = v0 * v0 + v1 * v1;
        #pragma unroll
        for (int o = 16; o > 0; o >>= 1) ss += __shfl_xor_sync(0xffffffffu, ss, o);

        float r = 1.0f / fmaxf(sqrtf(ss), EPS);
        vl[c * DIM + d0] = v0 * r;
        vl[c * DIM + d1] = v1 * r;
        if (lane == 0) local += ss * r * r;   // per-row sumsq after row normalize
    }
    if (lane == 0) wsum[w] = local;
    __syncthreads();

    // deterministic fixed-order global reduction
    float tot = 0.f;
    #pragma unroll
    for (int j = 0; j < 8; ++j) tot += wsum[j];
    const float rt = 1.0f / fmaxf(sqrtf(tot), EPS);

    for (int i = tid; i < FG * DIM; i += 256)
        out[b * (FG * DIM) + i] = vl[i] * rt;
}

// ---------------------------------------------------------------------------
extern "C" void kernel_launch(void* const* d_in, const int* in_sizes, int n_in,
                              void* d_out, int out_size) {
    const float* x         = (const float*)d_in[0];   // (32, 16384, 64) fp32
    const float* centroids = (const float*)d_in[1];   // (64, 36) fp32
    float* out             = (float*)d_out;           // (32, 2048) fp32

    (void)in_sizes; (void)n_in; (void)out_size;

    cudaFuncSetAttribute(vlad_main, cudaFuncAttributeMaxDynamicSharedMemorySize,
                         SM_TOT * (int)sizeof(float));

    vlad_main<<<dim3(SPLIT, BATCH), NT, SM_TOT * sizeof(float)>>>(x, centroids);
    vlad_finalize<<<BATCH, 256>>>(centroids, out);
}